// round 3
// baseline (speedup 1.0000x reference)
#include <cuda_runtime.h>
#include <math.h>

#define B_    256
#define C_    3
#define IMG_  32
#define P_    4
#define D_    256
#define H_    8
#define HD_   32
#define T_    64
#define T1_   65
#define MLPH_ 2048
#define HEADH_ 8192
#define NCLS_ 10
#define PDIM_ 48
#define ND_   (T1_*D_)   // 16640

// ---------------- scratch (device globals; no allocs allowed) ----------------
__device__ float g_out[B_*T1_*D_];        // residual stream  (B,65,256)
__device__ float g_h[B_*T1_*D_];          // LN output
__device__ float g_qkv[B_*T1_*3*D_];      // qkv projections
__device__ float g_m[B_*T1_*MLPH_];       // mlp hidden
__device__ float g_hid[B_*HEADH_];        // head hidden

// ---------------- patch embed + cls + positional encoding --------------------
__global__ void patch_embed_kernel(const float* __restrict__ x,
                                   const float* __restrict__ cls,
                                   const float* __restrict__ Wp,
                                   const float* __restrict__ bp,
                                   float* __restrict__ out) {
    int b = blockIdx.x;
    int t = blockIdx.y;           // 0..64 token
    int d = threadIdx.x;          // 0..255
    // positional encoding pe[t, d]
    int i = d >> 1;
    float div = expf(-(float)(2 * i) * (9.210340371976184f / 256.0f));
    float ang = (float)t * div;
    float pe = (d & 1) ? cosf(ang) : sinf(ang);

    if (t == 0) {
        out[(b * T1_) * D_ + d] = cls[d] + pe;
    } else {
        __shared__ float sp[PDIM_];
        int tt = t - 1;
        int ni = tt >> 3, nj = tt & 7;
        if (d < PDIM_) {
            int c  = d / 16;
            int pi = (d >> 2) & 3;
            int pj = d & 3;
            sp[d] = x[((b * C_ + c) * IMG_ + ni * 4 + pi) * IMG_ + nj * 4 + pj];
        }
        __syncthreads();
        float acc = bp[d];
        #pragma unroll
        for (int k = 0; k < PDIM_; k++) acc += sp[k] * Wp[k * D_ + d];
        out[((b * T1_) + t) * D_ + d] = acc + pe;
    }
}

// ---------------- LayerNorm over the whole (T1,D) slab per sample ------------
__global__ void ln2d_kernel(const float* __restrict__ X,
                            const float* __restrict__ w,
                            const float* __restrict__ bb,
                            float* __restrict__ Y) {
    int b = blockIdx.x;
    const float* xb = X + b * ND_;
    float s = 0.f, s2 = 0.f;
    for (int i = threadIdx.x; i < ND_; i += 256) {
        float v = xb[i];
        s += v; s2 += v * v;
    }
    __shared__ float rs[8], rs2[8], bc[2];
    #pragma unroll
    for (int o = 16; o > 0; o >>= 1) {
        s  += __shfl_down_sync(0xffffffffu, s,  o);
        s2 += __shfl_down_sync(0xffffffffu, s2, o);
    }
    int wid = threadIdx.x >> 5, lid = threadIdx.x & 31;
    if (lid == 0) { rs[wid] = s; rs2[wid] = s2; }
    __syncthreads();
    if (threadIdx.x == 0) {
        float ts = 0.f, ts2 = 0.f;
        #pragma unroll
        for (int k = 0; k < 8; k++) { ts += rs[k]; ts2 += rs2[k]; }
        float mu  = ts / (float)ND_;
        float var = ts2 / (float)ND_ - mu * mu;
        bc[0] = mu;
        bc[1] = rsqrtf(var + 1e-5f);
    }
    __syncthreads();
    float mu = bc[0], rsg = bc[1];
    float* yb = Y + b * ND_;
    for (int i = threadIdx.x; i < ND_; i += 256) {
        yb[i] = (xb[i] - mu) * rsg * w[i] + bb[i];
    }
}

// ---------------- generic tiled fp32 GEMM: C = act(A@W + bias) (+R) ----------
// A: (M,K) row-major, W: (K,N) row-major. All dims multiples of tile sizes.
// ACT: 0 none, 1 relu, 2 silu. RES: add R (M,N).
template<int ACT, bool RES>
__global__ void gemm64(const float* __restrict__ A, const float* __restrict__ W,
                       const float* __restrict__ bias, const float* __restrict__ R,
                       float* __restrict__ Cc, int M, int N, int K) {
    __shared__ float As[16][65];
    __shared__ float Bs[16][65];
    int tid = threadIdx.x;
    int tx = tid & 15, ty = tid >> 4;
    int m0 = blockIdx.y * 64, n0 = blockIdx.x * 64;
    float c[4][4] = {};
    for (int k0 = 0; k0 < K; k0 += 16) {
        #pragma unroll
        for (int i = 0; i < 4; i++) {
            int e = tid + i * 256;
            int m = e >> 4, k = e & 15;
            As[k][m] = A[(long)(m0 + m) * K + k0 + k];
            int kb = e >> 6, n = e & 63;
            Bs[kb][n] = W[(long)(k0 + kb) * N + n0 + n];
        }
        __syncthreads();
        #pragma unroll
        for (int kk = 0; kk < 16; kk++) {
            float a[4], bv[4];
            #pragma unroll
            for (int i = 0; i < 4; i++) { a[i] = As[kk][ty * 4 + i]; bv[i] = Bs[kk][tx * 4 + i]; }
            #pragma unroll
            for (int i = 0; i < 4; i++)
                #pragma unroll
                for (int j = 0; j < 4; j++)
                    c[i][j] += a[i] * bv[j];
        }
        __syncthreads();
    }
    #pragma unroll
    for (int i = 0; i < 4; i++) {
        int m = m0 + ty * 4 + i;
        #pragma unroll
        for (int j = 0; j < 4; j++) {
            int n = n0 + tx * 4 + j;
            float v = c[i][j] + bias[n];
            if (ACT == 1) v = fmaxf(v, 0.f);
            if (ACT == 2) v = v / (1.f + expf(-v));
            if (RES) v += R[(long)m * N + n];
            Cc[(long)m * N + n] = v;
        }
    }
}

// ---------------- fused attention per (b, h); writes r = attn + out in place -
__global__ void attn_kernel(const float* __restrict__ qkv, float* __restrict__ out) {
    int h = blockIdx.x, b = blockIdx.y;
    __shared__ float Ks[T1_][HD_];
    __shared__ float Vs[T1_][HD_];
    __shared__ float S[T1_][T1_ + 1];
    const float* base = qkv + (long)b * T1_ * 768 + h * 96;
    for (int idx = threadIdx.x; idx < T1_ * HD_; idx += blockDim.x) {
        int r = idx >> 5, d = idx & 31;
        Ks[r][d] = base[r * 768 + 32 + d];
        Vs[r][d] = base[r * 768 + 64 + d];
    }
    __syncthreads();
    int r = threadIdx.x;
    if (r < T1_) {
        float q[HD_];
        #pragma unroll
        for (int d = 0; d < HD_; d++) q[d] = base[r * 768 + d];
        float mx = -1e30f;
        for (int k = 0; k < T1_; k++) {
            float acc = 0.f;
            #pragma unroll
            for (int d = 0; d < HD_; d++) acc += q[d] * Ks[k][d];
            acc *= 0.17677669529663687f;   // 1/sqrt(32)
            S[r][k] = acc;
            mx = fmaxf(mx, acc);
        }
        float sum = 0.f;
        for (int k = 0; k < T1_; k++) {
            float e = expf(S[r][k] - mx);
            S[r][k] = e;
            sum += e;
        }
        float inv = 1.f / sum;
        float* op = out + ((long)b * T1_ + r) * D_ + h * HD_;
        #pragma unroll
        for (int d = 0; d < HD_; d++) {
            float acc = 0.f;
            for (int k = 0; k < T1_; k++) acc += S[r][k] * Vs[k][d];
            op[d] += acc * inv;            // residual add (unique writer per element)
        }
    }
}

// ---------------- final classifier head: (B,8192)@(8192,10)+b ---------------
__global__ void head2_kernel(const float* __restrict__ hid, const float* __restrict__ W2,
                             const float* __restrict__ b2, float* __restrict__ out) {
    int b = blockIdx.x;
    float acc[NCLS_] = {};
    for (int k = threadIdx.x; k < HEADH_; k += 256) {
        float hv = hid[(long)b * HEADH_ + k];
        #pragma unroll
        for (int c = 0; c < NCLS_; c++) acc[c] += hv * W2[k * NCLS_ + c];
    }
    __shared__ float red[256];
    for (int c = 0; c < NCLS_; c++) {
        red[threadIdx.x] = acc[c];
        __syncthreads();
        for (int o = 128; o > 0; o >>= 1) {
            if (threadIdx.x < o) red[threadIdx.x] += red[threadIdx.x + o];
            __syncthreads();
        }
        if (threadIdx.x == 0) out[b * NCLS_ + c] = red[0] + b2[c];
        __syncthreads();
    }
}

// -----------------------------------------------------------------------------
extern "C" void kernel_launch(void* const* d_in, const int* in_sizes, int n_in,
                              void* d_out, int out_size) {
    const float* x      = (const float*)d_in[0];
    const float* cls    = (const float*)d_in[1];
    const float* Wp     = (const float*)d_in[2];
    const float* bp     = (const float*)d_in[3];
    const float* qkv_w  = (const float*)d_in[4];
    const float* qkv_b  = (const float*)d_in[5];
    const float* ln_w   = (const float*)d_in[6];
    const float* ln_b   = (const float*)d_in[7];
    const float* mlp1_w = (const float*)d_in[8];
    const float* mlp1_b = (const float*)d_in[9];
    const float* mlp2_w = (const float*)d_in[10];
    const float* mlp2_b = (const float*)d_in[11];
    const float* h1w    = (const float*)d_in[12];
    const float* h1b    = (const float*)d_in[13];
    const float* h2w    = (const float*)d_in[14];
    const float* h2b    = (const float*)d_in[15];
    float* out = (float*)d_out;

    float *p_out, *p_h, *p_qkv, *p_m, *p_hid;
    cudaGetSymbolAddress((void**)&p_out, g_out);
    cudaGetSymbolAddress((void**)&p_h,   g_h);
    cudaGetSymbolAddress((void**)&p_qkv, g_qkv);
    cudaGetSymbolAddress((void**)&p_m,   g_m);
    cudaGetSymbolAddress((void**)&p_hid, g_hid);

    dim3 gPatch(B_, T1_);
    patch_embed_kernel<<<gPatch, 256>>>(x, cls, Wp, bp, p_out);

    const int Mt = B_ * T1_;   // 16640 rows
    for (int l = 0; l < 2; l++) {
        ln2d_kernel<<<B_, 256>>>(p_out, ln_w + l * ND_, ln_b + l * ND_, p_h);
        gemm64<0, false><<<dim3(768 / 64, Mt / 64), 256>>>(
            p_h, qkv_w + l * D_ * 768, qkv_b + l * 768, nullptr, p_qkv,
            Mt, 768, D_);
        attn_kernel<<<dim3(H_, B_), 128>>>(p_qkv, p_out);
        ln2d_kernel<<<B_, 256>>>(p_out, ln_w + l * ND_, ln_b + l * ND_, p_h);
        gemm64<1, false><<<dim3(MLPH_ / 64, Mt / 64), 256>>>(
            p_h, mlp1_w + l * D_ * MLPH_, mlp1_b + l * MLPH_, nullptr, p_m,
            Mt, MLPH_, D_);
        gemm64<0, true><<<dim3(D_ / 64, Mt / 64), 256>>>(
            p_m, mlp2_w + l * MLPH_ * D_, mlp2_b + l * D_, p_out, p_out,
            Mt, D_, MLPH_);
    }

    // head1: (256, 16640) @ (16640, 8192) + b, silu
    gemm64<2, false><<<dim3(HEADH_ / 64, B_ / 64), 256>>>(
        p_out, h1w, h1b, nullptr, p_hid, B_, HEADH_, ND_);

    head2_kernel<<<B_, 256>>>(p_hid, h2w, h2b, out);
}

// round 5
// speedup vs baseline: 1.9535x; 1.9535x over previous
#include <cuda_runtime.h>
#include <math.h>

#define B_    256
#define C_    3
#define IMG_  32
#define D_    256
#define H_    8
#define HD_   32
#define T1_   65
#define MLPH_ 2048
#define HEADH_ 8192
#define NCLS_ 10
#define PDIM_ 48
#define ND_   (T1_*D_)   // 16640

// ---------------- scratch ----------------------------------------------------
__device__ float g_out[B_*T1_*D_];
__device__ float g_h[B_*T1_*D_];
__device__ float g_qkv[B_*T1_*3*D_];
__device__ float g_m[B_*T1_*MLPH_];
__device__ float g_hid[B_*HEADH_];

// ---------------- f32x2 helpers ----------------------------------------------
__device__ __forceinline__ unsigned long long pk2(float x) {
    unsigned long long r;
    asm("mov.b64 %0, {%1, %1};" : "=l"(r) : "f"(x));
    return r;
}
__device__ __forceinline__ void ffma2(unsigned long long& c, unsigned long long a,
                                      unsigned long long b) {
    asm("fma.rn.f32x2 %0, %1, %2, %0;" : "+l"(c) : "l"(a), "l"(b));
}
__device__ __forceinline__ void upk(unsigned long long c, float& lo, float& hi) {
    asm("mov.b64 {%0, %1}, %2;" : "=f"(lo), "=f"(hi) : "l"(c));
}

// ---------------- patch embed + cls + positional encoding --------------------
__global__ void patch_embed_kernel(const float* __restrict__ x,
                                   const float* __restrict__ cls,
                                   const float* __restrict__ Wp,
                                   const float* __restrict__ bp,
                                   float* __restrict__ out) {
    int b = blockIdx.x;
    int t = blockIdx.y;
    int d = threadIdx.x;
    int i = d >> 1;
    float div = expf(-(float)(2 * i) * (9.210340371976184f / 256.0f));
    float ang = (float)t * div;
    float pe = (d & 1) ? cosf(ang) : sinf(ang);

    if (t == 0) {
        out[(b * T1_) * D_ + d] = cls[d] + pe;
    } else {
        __shared__ float sp[PDIM_];
        int tt = t - 1;
        int ni = tt >> 3, nj = tt & 7;
        if (d < PDIM_) {
            int c  = d / 16;
            int pi = (d >> 2) & 3;
            int pj = d & 3;
            sp[d] = x[((b * C_ + c) * IMG_ + ni * 4 + pi) * IMG_ + nj * 4 + pj];
        }
        __syncthreads();
        float acc = bp[d];
        #pragma unroll
        for (int k = 0; k < PDIM_; k++) acc += sp[k] * Wp[k * D_ + d];
        out[((b * T1_) + t) * D_ + d] = acc + pe;
    }
}

// ---------------- LayerNorm over whole (T1,D) slab per sample ----------------
__global__ void ln2d_kernel(const float* __restrict__ X,
                            const float* __restrict__ w,
                            const float* __restrict__ bb,
                            float* __restrict__ Y) {
    int b = blockIdx.x;
    const float* xb = X + b * ND_;
    float s = 0.f, s2 = 0.f;
    for (int i = threadIdx.x; i < ND_; i += 256) {
        float v = xb[i];
        s += v; s2 += v * v;
    }
    __shared__ float rs[8], rs2[8], bc[2];
    #pragma unroll
    for (int o = 16; o > 0; o >>= 1) {
        s  += __shfl_down_sync(0xffffffffu, s,  o);
        s2 += __shfl_down_sync(0xffffffffu, s2, o);
    }
    int wid = threadIdx.x >> 5, lid = threadIdx.x & 31;
    if (lid == 0) { rs[wid] = s; rs2[wid] = s2; }
    __syncthreads();
    if (threadIdx.x == 0) {
        float ts = 0.f, ts2 = 0.f;
        #pragma unroll
        for (int k = 0; k < 8; k++) { ts += rs[k]; ts2 += rs2[k]; }
        float mu  = ts / (float)ND_;
        float var = ts2 / (float)ND_ - mu * mu;
        bc[0] = mu;
        bc[1] = rsqrtf(var + 1e-5f);
    }
    __syncthreads();
    float mu = bc[0], rsg = bc[1];
    float* yb = Y + b * ND_;
    for (int i = threadIdx.x; i < ND_; i += 256) {
        yb[i] = (xb[i] - mu) * rsg * w[i] + bb[i];
    }
}

// ---------------- FFMA2 SGEMM: 128x128 tile, BK=16, 256 thr, 8x8 microtile ---
// A (M,K) row-major, W (K,N) row-major. M%128==0, N%128==0, K%16==0.
// ACT: 0 none, 1 relu, 2 silu. RES: add R (M,N).
template<int ACT, bool RES>
__global__ __launch_bounds__(256, 2)
void gemm128(const float* __restrict__ A, const float* __restrict__ W,
             const float* __restrict__ bias, const float* __restrict__ R,
             float* __restrict__ Cc, int M, int N, int K) {
    __shared__ __align__(16) float As[2][16 * 132];  // [k][m], padded
    __shared__ __align__(16) float Bs[2][16 * 128];  // [k][n]

    const int tid = threadIdx.x;
    const int tx = tid & 15, ty = tid >> 4;
    const int m0 = blockIdx.y * 128, n0 = blockIdx.x * 128;

    // global-load indices
    const int arow = tid >> 2, akq = (tid & 3) << 2;          // A: 128 rows x 16k, 1 f4/thr + second
    const int bkr = tid >> 5, bc4 = (tid & 31) << 2;          // B: 16 rows x 128 cols

    unsigned long long c[8][4];
    #pragma unroll
    for (int i = 0; i < 8; i++)
        #pragma unroll
        for (int j = 0; j < 4; j++) c[i][j] = 0ull;

    float4 ra[2], rb[2];
    const int nt = K >> 4;

    // prologue: load tile 0
    #pragma unroll
    for (int i = 0; i < 2; i++) {
        int idx = tid + i * 256;
        int row = idx >> 2, kq = (idx & 3) << 2;
        ra[i] = *(const float4*)&A[(long)(m0 + row) * K + kq];
        int kr = idx >> 5, c4 = (idx & 31) << 2;
        rb[i] = *(const float4*)&W[(long)kr * N + n0 + c4];
    }
    #pragma unroll
    for (int i = 0; i < 2; i++) {
        int idx = tid + i * 256;
        int row = idx >> 2, kq = (idx & 3) << 2;
        As[0][(kq + 0) * 132 + row] = ra[i].x;
        As[0][(kq + 1) * 132 + row] = ra[i].y;
        As[0][(kq + 2) * 132 + row] = ra[i].z;
        As[0][(kq + 3) * 132 + row] = ra[i].w;
        int kr = idx >> 5, c4 = (idx & 31) << 2;
        *(float4*)&Bs[0][kr * 128 + c4] = rb[i];
    }
    __syncthreads();

    for (int t = 0; t < nt; t++) {
        const int buf = t & 1;
        const bool has = (t + 1) < nt;
        if (has) {
            const int k0 = (t + 1) << 4;
            #pragma unroll
            for (int i = 0; i < 2; i++) {
                int idx = tid + i * 256;
                int row = idx >> 2, kq = (idx & 3) << 2;
                ra[i] = *(const float4*)&A[(long)(m0 + row) * K + k0 + kq];
                int kr = idx >> 5, c4 = (idx & 31) << 2;
                rb[i] = *(const float4*)&W[(long)(k0 + kr) * N + n0 + c4];
            }
        }

        #pragma unroll
        for (int kk = 0; kk < 16; kk++) {
            const float4 a0 = *(const float4*)&As[buf][kk * 132 + ty * 4];
            const float4 a1 = *(const float4*)&As[buf][kk * 132 + 64 + ty * 4];
            const ulonglong2 b0 = *(const ulonglong2*)&Bs[buf][kk * 128 + tx * 4];
            const ulonglong2 b1 = *(const ulonglong2*)&Bs[buf][kk * 128 + 64 + tx * 4];
            float av[8] = {a0.x, a0.y, a0.z, a0.w, a1.x, a1.y, a1.z, a1.w};
            unsigned long long bv[4] = {b0.x, b0.y, b1.x, b1.y};
            #pragma unroll
            for (int i = 0; i < 8; i++) {
                unsigned long long aa = pk2(av[i]);
                ffma2(c[i][0], aa, bv[0]);
                ffma2(c[i][1], aa, bv[1]);
                ffma2(c[i][2], aa, bv[2]);
                ffma2(c[i][3], aa, bv[3]);
            }
        }

        if (has) {
            const int nb = buf ^ 1;
            #pragma unroll
            for (int i = 0; i < 2; i++) {
                int idx = tid + i * 256;
                int row = idx >> 2, kq = (idx & 3) << 2;
                As[nb][(kq + 0) * 132 + row] = ra[i].x;
                As[nb][(kq + 1) * 132 + row] = ra[i].y;
                As[nb][(kq + 2) * 132 + row] = ra[i].z;
                As[nb][(kq + 3) * 132 + row] = ra[i].w;
                int kr = idx >> 5, c4 = (idx & 31) << 2;
                *(float4*)&Bs[nb][kr * 128 + c4] = rb[i];
            }
        }
        __syncthreads();
    }

    // epilogue
    const float4 bia0 = *(const float4*)&bias[n0 + tx * 4];
    const float4 bia1 = *(const float4*)&bias[n0 + 64 + tx * 4];
    const float bb0[4] = {bia0.x, bia0.y, bia0.z, bia0.w};
    const float bb1[4] = {bia1.x, bia1.y, bia1.z, bia1.w};
    #pragma unroll
    for (int rh = 0; rh < 2; rh++) {
        #pragma unroll
        for (int i = 0; i < 4; i++) {
            const int m = m0 + rh * 64 + ty * 4 + i;
            const int ci = rh * 4 + i;
            #pragma unroll
            for (int ch = 0; ch < 2; ch++) {
                const int n = n0 + ch * 64 + tx * 4;
                float f[4];
                upk(c[ci][ch * 2 + 0], f[0], f[1]);
                upk(c[ci][ch * 2 + 1], f[2], f[3]);
                const float* bbv = ch ? bb1 : bb0;
                float4 o;
                float* op = &o.x;
                #pragma unroll
                for (int j = 0; j < 4; j++) {
                    float v = f[j] + bbv[j];
                    if (ACT == 1) v = fmaxf(v, 0.f);
                    if (ACT == 2) v = v / (1.f + expf(-v));
                    op[j] = v;
                }
                if (RES) {
                    const float4 r4 = *(const float4*)&R[(long)m * N + n];
                    o.x += r4.x; o.y += r4.y; o.z += r4.z; o.w += r4.w;
                }
                *(float4*)&Cc[(long)m * N + n] = o;
            }
        }
    }
}

// ---------------- fused attention per (b,h); out += attn (residual) ----------
__global__ __launch_bounds__(96)
void attn_kernel(const float* __restrict__ qkv, float* __restrict__ out) {
    const int h = blockIdx.x, b = blockIdx.y;
    __shared__ __align__(16) float Ks[T1_ * 32];
    __shared__ __align__(16) float Vs[T1_ * 32];
    __shared__ float S[T1_ * 67];
    const float* base = qkv + (long)b * T1_ * 768 + h * 96;

    for (int idx = threadIdx.x; idx < T1_ * 8; idx += 96) {
        int r = idx >> 3, c4 = (idx & 7) << 2;
        *(float4*)&Ks[r * 32 + c4] = *(const float4*)&base[r * 768 + 32 + c4];
        *(float4*)&Vs[r * 32 + c4] = *(const float4*)&base[r * 768 + 64 + c4];
    }
    __syncthreads();

    const int r = threadIdx.x;
    if (r < T1_) {
        float4 q4[8];
        #pragma unroll
        for (int j = 0; j < 8; j++)
            q4[j] = *(const float4*)&base[r * 768 + j * 4];

        float mx = -1e30f;
        for (int k = 0; k < T1_; k++) {
            float acc = 0.f;
            #pragma unroll
            for (int j = 0; j < 8; j++) {
                const float4 kv = *(const float4*)&Ks[k * 32 + j * 4];
                acc += q4[j].x * kv.x + q4[j].y * kv.y + q4[j].z * kv.z + q4[j].w * kv.w;
            }
            acc *= 0.17677669529663687f;
            S[r * 67 + k] = acc;
            mx = fmaxf(mx, acc);
        }
        float sum = 0.f;
        for (int k = 0; k < T1_; k++) {
            float e = expf(S[r * 67 + k] - mx);
            S[r * 67 + k] = e;
            sum += e;
        }
        const float inv = 1.f / sum;

        float4 acc4[8];
        #pragma unroll
        for (int j = 0; j < 8; j++) acc4[j] = make_float4(0.f, 0.f, 0.f, 0.f);
        for (int k = 0; k < T1_; k++) {
            const float s = S[r * 67 + k];
            #pragma unroll
            for (int j = 0; j < 8; j++) {
                const float4 vv = *(const float4*)&Vs[k * 32 + j * 4];
                acc4[j].x += s * vv.x; acc4[j].y += s * vv.y;
                acc4[j].z += s * vv.z; acc4[j].w += s * vv.w;
            }
        }
        float* op = out + ((long)b * T1_ + r) * D_ + h * HD_;
        #pragma unroll
        for (int j = 0; j < 8; j++) {
            float4 o = *(float4*)&op[j * 4];
            o.x += acc4[j].x * inv; o.y += acc4[j].y * inv;
            o.z += acc4[j].z * inv; o.w += acc4[j].w * inv;
            *(float4*)&op[j * 4] = o;
        }
    }
}

// ---------------- final classifier head --------------------------------------
__global__ void head2_kernel(const float* __restrict__ hid, const float* __restrict__ W2,
                             const float* __restrict__ b2, float* __restrict__ out) {
    int b = blockIdx.x;
    float acc[NCLS_] = {};
    for (int k = threadIdx.x; k < HEADH_; k += 256) {
        float hv = hid[(long)b * HEADH_ + k];
        #pragma unroll
        for (int c = 0; c < NCLS_; c++) acc[c] += hv * W2[k * NCLS_ + c];
    }
    __shared__ float red[256];
    for (int c = 0; c < NCLS_; c++) {
        red[threadIdx.x] = acc[c];
        __syncthreads();
        for (int o = 128; o > 0; o >>= 1) {
            if (threadIdx.x < o) red[threadIdx.x] += red[threadIdx.x + o];
            __syncthreads();
        }
        if (threadIdx.x == 0) out[b * NCLS_ + c] = red[0] + b2[c];
        __syncthreads();
    }
}

// -----------------------------------------------------------------------------
extern "C" void kernel_launch(void* const* d_in, const int* in_sizes, int n_in,
                              void* d_out, int out_size) {
    const float* x      = (const float*)d_in[0];
    const float* cls    = (const float*)d_in[1];
    const float* Wp     = (const float*)d_in[2];
    const float* bp     = (const float*)d_in[3];
    const float* qkv_w  = (const float*)d_in[4];
    const float* qkv_b  = (const float*)d_in[5];
    const float* ln_w   = (const float*)d_in[6];
    const float* ln_b   = (const float*)d_in[7];
    const float* mlp1_w = (const float*)d_in[8];
    const float* mlp1_b = (const float*)d_in[9];
    const float* mlp2_w = (const float*)d_in[10];
    const float* mlp2_b = (const float*)d_in[11];
    const float* h1w    = (const float*)d_in[12];
    const float* h1b    = (const float*)d_in[13];
    const float* h2w    = (const float*)d_in[14];
    const float* h2b    = (const float*)d_in[15];
    float* out = (float*)d_out;

    float *p_out, *p_h, *p_qkv, *p_m, *p_hid;
    cudaGetSymbolAddress((void**)&p_out, g_out);
    cudaGetSymbolAddress((void**)&p_h,   g_h);
    cudaGetSymbolAddress((void**)&p_qkv, g_qkv);
    cudaGetSymbolAddress((void**)&p_m,   g_m);
    cudaGetSymbolAddress((void**)&p_hid, g_hid);

    dim3 gPatch(B_, T1_);
    patch_embed_kernel<<<gPatch, 256>>>(x, cls, Wp, bp, p_out);

    const int Mt = B_ * T1_;   // 16640
    for (int l = 0; l < 2; l++) {
        ln2d_kernel<<<B_, 256>>>(p_out, ln_w + l * ND_, ln_b + l * ND_, p_h);
        gemm128<0, false><<<dim3(768 / 128, Mt / 128), 256>>>(
            p_h, qkv_w + l * D_ * 768, qkv_b + l * 768, nullptr, p_qkv,
            Mt, 768, D_);
        attn_kernel<<<dim3(H_, B_), 96>>>(p_qkv, p_out);
        ln2d_kernel<<<B_, 256>>>(p_out, ln_w + l * ND_, ln_b + l * ND_, p_h);
        gemm128<1, false><<<dim3(MLPH_ / 128, Mt / 128), 256>>>(
            p_h, mlp1_w + l * D_ * MLPH_, mlp1_b + l * MLPH_, nullptr, p_m,
            Mt, MLPH_, D_);
        gemm128<0, true><<<dim3(D_ / 128, Mt / 128), 256>>>(
            p_m, mlp2_w + l * MLPH_ * D_, mlp2_b + l * D_, p_out, p_out,
            Mt, D_, MLPH_);
    }

    gemm128<2, false><<<dim3(HEADH_ / 128, B_ / 128), 256>>>(
        p_out, h1w, h1b, nullptr, p_hid, B_, HEADH_, ND_);

    head2_kernel<<<B_, 256>>>(p_hid, h2w, h2b, out);
}

// round 7
// speedup vs baseline: 3.7432x; 1.9162x over previous
#include <cuda_runtime.h>
#include <cuda_bf16.h>
#include <math.h>
#include <stdint.h>

#define B_    256
#define C_    3
#define IMG_  32
#define D_    256
#define H_    8
#define HD_   32
#define T1_   65
#define MLPH_ 2048
#define HEADH_ 8192
#define NCLS_ 10
#define PDIM_ 48
#define ND_   (T1_*D_)   // 16640

// ---------------- scratch ----------------------------------------------------
__device__ float g_out[B_*T1_*D_];
__device__ float g_h[B_*T1_*D_];
__device__ float g_qkv[B_*T1_*3*D_];
__device__ float g_m[B_*T1_*MLPH_];
__device__ float g_hid[B_*HEADH_];

// ---------------- patch embed + cls + positional encoding --------------------
__global__ void patch_embed_kernel(const float* __restrict__ x,
                                   const float* __restrict__ cls,
                                   const float* __restrict__ Wp,
                                   const float* __restrict__ bp,
                                   float* __restrict__ out) {
    int b = blockIdx.x;
    int t = blockIdx.y;
    int d = threadIdx.x;
    int i = d >> 1;
    float div = expf(-(float)(2 * i) * (9.210340371976184f / 256.0f));
    float ang = (float)t * div;
    float pe = (d & 1) ? cosf(ang) : sinf(ang);

    if (t == 0) {
        out[(b * T1_) * D_ + d] = cls[d] + pe;
    } else {
        __shared__ float sp[PDIM_];
        int tt = t - 1;
        int ni = tt >> 3, nj = tt & 7;
        if (d < PDIM_) {
            int c  = d / 16;
            int pi = (d >> 2) & 3;
            int pj = d & 3;
            sp[d] = x[((b * C_ + c) * IMG_ + ni * 4 + pi) * IMG_ + nj * 4 + pj];
        }
        __syncthreads();
        float acc = bp[d];
        #pragma unroll
        for (int k = 0; k < PDIM_; k++) acc += sp[k] * Wp[k * D_ + d];
        out[((b * T1_) + t) * D_ + d] = acc + pe;
    }
}

// ---------------- LayerNorm over whole (T1,D) slab per sample ----------------
__global__ void ln2d_kernel(const float* __restrict__ X,
                            const float* __restrict__ w,
                            const float* __restrict__ bb,
                            float* __restrict__ Y) {
    int b = blockIdx.x;
    const float* xb = X + b * ND_;
    float s = 0.f, s2 = 0.f;
    for (int i = threadIdx.x; i < ND_; i += 256) {
        float v = xb[i];
        s += v; s2 += v * v;
    }
    __shared__ float rs[8], rs2[8], bc[2];
    #pragma unroll
    for (int o = 16; o > 0; o >>= 1) {
        s  += __shfl_down_sync(0xffffffffu, s,  o);
        s2 += __shfl_down_sync(0xffffffffu, s2, o);
    }
    int wid = threadIdx.x >> 5, lid = threadIdx.x & 31;
    if (lid == 0) { rs[wid] = s; rs2[wid] = s2; }
    __syncthreads();
    if (threadIdx.x == 0) {
        float ts = 0.f, ts2 = 0.f;
        #pragma unroll
        for (int k = 0; k < 8; k++) { ts += rs[k]; ts2 += rs2[k]; }
        float mu  = ts / (float)ND_;
        float var = ts2 / (float)ND_ - mu * mu;
        bc[0] = mu;
        bc[1] = rsqrtf(var + 1e-5f);
    }
    __syncthreads();
    float mu = bc[0], rsg = bc[1];
    float* yb = Y + b * ND_;
    for (int i = threadIdx.x; i < ND_; i += 256) {
        yb[i] = (xb[i] - mu) * rsg * w[i] + bb[i];
    }
}

// ---------------- bf16-split tensor-core GEMM (mma.sync m16n8k16) ------------
// C(M,N) = act(A(M,K) @ W(K,N) + bias) (+R). fp32 = bf16_hi + bf16_lo,
// C ~= AhWh + AhWl + AlWh, fp32 accumulate.
// Tile 128x128, BK=32, 8 warps, warp tile 64x32 (4x4 m16n8k16 atoms).
#define PITCH 40                              // bf16 elements per smem row
#define REG_A 0                               // byte offsets inside one buffer
#define REG_AL 10240
#define REG_BH 20480
#define REG_BL 30720
#define BUFSZ 40960
#define GSMEM_TOTAL (2*BUFSZ)

__device__ __forceinline__ void mma16816(float* c, const uint32_t* a, const uint32_t* b) {
    asm volatile(
        "mma.sync.aligned.m16n8k16.row.col.f32.bf16.bf16.f32 "
        "{%0,%1,%2,%3}, {%4,%5,%6,%7}, {%8,%9}, {%0,%1,%2,%3};"
        : "+f"(c[0]), "+f"(c[1]), "+f"(c[2]), "+f"(c[3])
        : "r"(a[0]), "r"(a[1]), "r"(a[2]), "r"(a[3]), "r"(b[0]), "r"(b[1]));
}
__device__ __forceinline__ void split_pair(float x, float y,
                                           __nv_bfloat162& hi, __nv_bfloat162& lo) {
    hi = __float22bfloat162_rn(make_float2(x, y));
    float2 hf = __bfloat1622float2(hi);
    lo = __float22bfloat162_rn(make_float2(x - hf.x, y - hf.y));
}

template<int ACT, bool RES>
__global__ void __launch_bounds__(256) gemm_tc(
    const float* __restrict__ A, const float* __restrict__ W,
    const float* __restrict__ bias, const float* __restrict__ R,
    float* __restrict__ Cc, int M, int N, int K)
{
    extern __shared__ char smem[];
    const int tid = threadIdx.x;
    const int wid = tid >> 5;
    const int lane = tid & 31;
    const int wm = wid >> 2, wn = wid & 3;       // warp grid 2x4 -> 64x32 tiles
    const int m0 = blockIdx.y * 128, n0 = blockIdx.x * 128;
    const int gid = lane >> 2, tig = lane & 3;   // mma fragment indices

    // B-fill assignment
    const int bn = tid & 127;
    const int bkh = (tid >> 7) * 16;

    float c[4][4][4];
    #pragma unroll
    for (int i = 0; i < 4; i++)
        #pragma unroll
        for (int j = 0; j < 4; j++)
            #pragma unroll
            for (int r = 0; r < 4; r++) c[i][j][r] = 0.f;

    const int nk = K / 32;
    float4 ra[4];
    float rb[16];

    // ---- LDG tile t into regs ----
    auto ldg_tile = [&](int t) {
        #pragma unroll
        for (int i = 0; i < 4; i++) {
            int lin = tid + i * 256;
            int row = lin >> 3, q = lin & 7;
            ra[i] = *(const float4*)&A[(long)(m0 + row) * K + t * 32 + q * 4];
        }
        const float* Wb = W + (long)(t * 32 + bkh) * N + n0 + bn;
        #pragma unroll
        for (int p = 0; p < 16; p++) rb[p] = Wb[(long)p * N];
    };
    // ---- convert + STS into buffer ----
    auto sts_tile = [&](int buf) {
        char* base = smem + buf * BUFSZ;
        #pragma unroll
        for (int i = 0; i < 4; i++) {
            int lin = tid + i * 256;
            int row = lin >> 3, q = lin & 7;
            __nv_bfloat162 h0, l0, h1, l1;
            split_pair(ra[i].x, ra[i].y, h0, l0);
            split_pair(ra[i].z, ra[i].w, h1, l1);
            int e = row * PITCH + q * 4;
            *(__nv_bfloat162*)(base + REG_A  + e * 2)     = h0;
            *(__nv_bfloat162*)(base + REG_A  + e * 2 + 4) = h1;
            *(__nv_bfloat162*)(base + REG_AL + e * 2)     = l0;
            *(__nv_bfloat162*)(base + REG_AL + e * 2 + 4) = l1;
        }
        #pragma unroll
        for (int p = 0; p < 8; p++) {
            __nv_bfloat162 h, l;
            split_pair(rb[2 * p], rb[2 * p + 1], h, l);
            int e = bn * PITCH + bkh + 2 * p;
            *(__nv_bfloat162*)(base + REG_BH + e * 2) = h;
            *(__nv_bfloat162*)(base + REG_BL + e * 2) = l;
        }
    };

    ldg_tile(0);
    sts_tile(0);
    __syncthreads();

    for (int t = 0; t < nk; t++) {
        const int buf = t & 1;
        if (t + 1 < nk) ldg_tile(t + 1);

        const char* ahp = smem + buf * BUFSZ + REG_A;
        const char* alp = smem + buf * BUFSZ + REG_AL;
        const char* bhp = smem + buf * BUFSZ + REG_BH;
        const char* blp = smem + buf * BUFSZ + REG_BL;

        #pragma unroll
        for (int ks = 0; ks < 2; ks++) {
            uint32_t ah[4][4], al[4][4], bh[4][2], bl[4][2];
            const int acol = ks * 16 + tig * 2;
            #pragma unroll
            for (int am = 0; am < 4; am++) {
                const int arow = wm * 64 + am * 16 + gid;
                const int e00 = (arow * PITCH + acol) * 2;
                const int e10 = ((arow + 8) * PITCH + acol) * 2;
                ah[am][0] = *(const uint32_t*)(ahp + e00);
                ah[am][1] = *(const uint32_t*)(ahp + e10);
                ah[am][2] = *(const uint32_t*)(ahp + e00 + 16);
                ah[am][3] = *(const uint32_t*)(ahp + e10 + 16);
                al[am][0] = *(const uint32_t*)(alp + e00);
                al[am][1] = *(const uint32_t*)(alp + e10);
                al[am][2] = *(const uint32_t*)(alp + e00 + 16);
                al[am][3] = *(const uint32_t*)(alp + e10 + 16);
            }
            #pragma unroll
            for (int an = 0; an < 4; an++) {
                const int brow = wn * 32 + an * 8 + gid;
                const int e = (brow * PITCH + acol) * 2;
                bh[an][0] = *(const uint32_t*)(bhp + e);
                bh[an][1] = *(const uint32_t*)(bhp + e + 16);
                bl[an][0] = *(const uint32_t*)(blp + e);
                bl[an][1] = *(const uint32_t*)(blp + e + 16);
            }
            #pragma unroll
            for (int am = 0; am < 4; am++)
                #pragma unroll
                for (int an = 0; an < 4; an++) {
                    mma16816(c[am][an], ah[am], bh[an]);
                    mma16816(c[am][an], ah[am], bl[an]);
                    mma16816(c[am][an], al[am], bh[an]);
                }
        }

        if (t + 1 < nk) sts_tile(buf ^ 1);
        __syncthreads();
    }

    // ---- epilogue ----
    #pragma unroll
    for (int am = 0; am < 4; am++) {
        #pragma unroll
        for (int an = 0; an < 4; an++) {
            const int col = n0 + wn * 32 + an * 8 + tig * 2;
            const float bx = bias[col], by = bias[col + 1];
            #pragma unroll
            for (int hrow = 0; hrow < 2; hrow++) {
                const int m = m0 + wm * 64 + am * 16 + gid + hrow * 8;
                float vx = c[am][an][hrow * 2 + 0] + bx;
                float vy = c[am][an][hrow * 2 + 1] + by;
                if (ACT == 1) { vx = fmaxf(vx, 0.f); vy = fmaxf(vy, 0.f); }
                if (ACT == 2) {
                    vx = vx / (1.f + expf(-vx));
                    vy = vy / (1.f + expf(-vy));
                }
                if (RES) {
                    const float2 r2 = *(const float2*)&R[(long)m * N + col];
                    vx += r2.x; vy += r2.y;
                }
                *(float2*)&Cc[(long)m * N + col] = make_float2(vx, vy);
            }
        }
    }
}

// ---------------- fused attention per (b,h); out += attn (residual) ----------
__global__ __launch_bounds__(96)
void attn_kernel(const float* __restrict__ qkv, float* __restrict__ out) {
    const int h = blockIdx.x, b = blockIdx.y;
    __shared__ __align__(16) float Ks[T1_ * 32];
    __shared__ __align__(16) float Vs[T1_ * 32];
    __shared__ float S[T1_ * 67];
    const float* base = qkv + (long)b * T1_ * 768 + h * 96;

    for (int idx = threadIdx.x; idx < T1_ * 8; idx += 96) {
        int r = idx >> 3, c4 = (idx & 7) << 2;
        *(float4*)&Ks[r * 32 + c4] = *(const float4*)&base[r * 768 + 32 + c4];
        *(float4*)&Vs[r * 32 + c4] = *(const float4*)&base[r * 768 + 64 + c4];
    }
    __syncthreads();

    const int r = threadIdx.x;
    if (r < T1_) {
        float4 q4[8];
        #pragma unroll
        for (int j = 0; j < 8; j++)
            q4[j] = *(const float4*)&base[r * 768 + j * 4];

        float mx = -1e30f;
        for (int k = 0; k < T1_; k++) {
            float acc = 0.f;
            #pragma unroll
            for (int j = 0; j < 8; j++) {
                const float4 kv = *(const float4*)&Ks[k * 32 + j * 4];
                acc += q4[j].x * kv.x + q4[j].y * kv.y + q4[j].z * kv.z + q4[j].w * kv.w;
            }
            acc *= 0.17677669529663687f;
            S[r * 67 + k] = acc;
            mx = fmaxf(mx, acc);
        }
        float sum = 0.f;
        for (int k = 0; k < T1_; k++) {
            float e = expf(S[r * 67 + k] - mx);
            S[r * 67 + k] = e;
            sum += e;
        }
        const float inv = 1.f / sum;

        float4 acc4[8];
        #pragma unroll
        for (int j = 0; j < 8; j++) acc4[j] = make_float4(0.f, 0.f, 0.f, 0.f);
        for (int k = 0; k < T1_; k++) {
            const float s = S[r * 67 + k];
            #pragma unroll
            for (int j = 0; j < 8; j++) {
                const float4 vv = *(const float4*)&Vs[k * 32 + j * 4];
                acc4[j].x += s * vv.x; acc4[j].y += s * vv.y;
                acc4[j].z += s * vv.z; acc4[j].w += s * vv.w;
            }
        }
        float* op = out + ((long)b * T1_ + r) * D_ + h * HD_;
        #pragma unroll
        for (int j = 0; j < 8; j++) {
            float4 o = *(float4*)&op[j * 4];
            o.x += acc4[j].x * inv; o.y += acc4[j].y * inv;
            o.z += acc4[j].z * inv; o.w += acc4[j].w * inv;
            *(float4*)&op[j * 4] = o;
        }
    }
}

// ---------------- final classifier head --------------------------------------
__global__ void head2_kernel(const float* __restrict__ hid, const float* __restrict__ W2,
                             const float* __restrict__ b2, float* __restrict__ out) {
    int b = blockIdx.x;
    float acc[NCLS_] = {};
    for (int k = threadIdx.x; k < HEADH_; k += 256) {
        float hv = hid[(long)b * HEADH_ + k];
        #pragma unroll
        for (int c = 0; c < NCLS_; c++) acc[c] += hv * W2[k * NCLS_ + c];
    }
    __shared__ float red[256];
    for (int c = 0; c < NCLS_; c++) {
        red[threadIdx.x] = acc[c];
        __syncthreads();
        for (int o = 128; o > 0; o >>= 1) {
            if (threadIdx.x < o) red[threadIdx.x] += red[threadIdx.x + o];
            __syncthreads();
        }
        if (threadIdx.x == 0) out[b * NCLS_ + c] = red[0] + b2[c];
        __syncthreads();
    }
}

// -----------------------------------------------------------------------------
extern "C" void kernel_launch(void* const* d_in, const int* in_sizes, int n_in,
                              void* d_out, int out_size) {
    const float* x      = (const float*)d_in[0];
    const float* cls    = (const float*)d_in[1];
    const float* Wp     = (const float*)d_in[2];
    const float* bp     = (const float*)d_in[3];
    const float* qkv_w  = (const float*)d_in[4];
    const float* qkv_b  = (const float*)d_in[5];
    const float* ln_w   = (const float*)d_in[6];
    const float* ln_b   = (const float*)d_in[7];
    const float* mlp1_w = (const float*)d_in[8];
    const float* mlp1_b = (const float*)d_in[9];
    const float* mlp2_w = (const float*)d_in[10];
    const float* mlp2_b = (const float*)d_in[11];
    const float* h1w    = (const float*)d_in[12];
    const float* h1b    = (const float*)d_in[13];
    const float* h2w    = (const float*)d_in[14];
    const float* h2b    = (const float*)d_in[15];
    float* out = (float*)d_out;

    float *p_out, *p_h, *p_qkv, *p_m, *p_hid;
    cudaGetSymbolAddress((void**)&p_out, g_out);
    cudaGetSymbolAddress((void**)&p_h,   g_h);
    cudaGetSymbolAddress((void**)&p_qkv, g_qkv);
    cudaGetSymbolAddress((void**)&p_m,   g_m);
    cudaGetSymbolAddress((void**)&p_hid, g_hid);

    cudaFuncSetAttribute(gemm_tc<0,false>, cudaFuncAttributeMaxDynamicSharedMemorySize, GSMEM_TOTAL);
    cudaFuncSetAttribute(gemm_tc<1,false>, cudaFuncAttributeMaxDynamicSharedMemorySize, GSMEM_TOTAL);
    cudaFuncSetAttribute(gemm_tc<0,true>,  cudaFuncAttributeMaxDynamicSharedMemorySize, GSMEM_TOTAL);
    cudaFuncSetAttribute(gemm_tc<2,false>, cudaFuncAttributeMaxDynamicSharedMemorySize, GSMEM_TOTAL);

    dim3 gPatch(B_, T1_);
    patch_embed_kernel<<<gPatch, 256>>>(x, cls, Wp, bp, p_out);

    const int Mt = B_ * T1_;   // 16640
    for (int l = 0; l < 2; l++) {
        ln2d_kernel<<<B_, 256>>>(p_out, ln_w + l * ND_, ln_b + l * ND_, p_h);
        gemm_tc<0, false><<<dim3(768 / 128, Mt / 128), 256, GSMEM_TOTAL>>>(
            p_h, qkv_w + l * D_ * 768, qkv_b + l * 768, nullptr, p_qkv,
            Mt, 768, D_);
        attn_kernel<<<dim3(H_, B_), 96>>>(p_qkv, p_out);
        ln2d_kernel<<<B_, 256>>>(p_out, ln_w + l * ND_, ln_b + l * ND_, p_h);
        gemm_tc<1, false><<<dim3(MLPH_ / 128, Mt / 128), 256, GSMEM_TOTAL>>>(
            p_h, mlp1_w + l * D_ * MLPH_, mlp1_b + l * MLPH_, nullptr, p_m,
            Mt, MLPH_, D_);
        gemm_tc<0, true><<<dim3(D_ / 128, Mt / 128), 256, GSMEM_TOTAL>>>(
            p_m, mlp2_w + l * MLPH_ * D_, mlp2_b + l * D_, p_out, p_out,
            Mt, D_, MLPH_);
    }

    gemm_tc<2, false><<<dim3(HEADH_ / 128, B_ / 128), 256, GSMEM_TOTAL>>>(
        p_out, h1w, h1b, nullptr, p_hid, B_, HEADH_, ND_);

    head2_kernel<<<B_, 256>>>(p_hid, h2w, h2b, out);
}